// round 2
// baseline (speedup 1.0000x reference)
#include <cuda_runtime.h>
#include <math.h>

#define N_NODES 50000
#define N_EDGES 800000
#define DD      128
#define EPSBN   1e-5f

#define TM 64                   // rows (nodes or edges) per GEMM tile
#define WT_STRIDE 132           // padded k-major W stride (conflict-free)
#define WT_FLOATS (128 * WT_STRIDE)
#define AT_FLOATS (TM * 128)
#define SMEM_FLOATS (WT_FLOATS + AT_FLOATS + 128)
#define SMEM_BYTES  (SMEM_FLOATS * 4)

// ---------------- scratch (static device allocations) ----------------
__device__ float g_Ah[N_NODES * DD];
__device__ float g_Bh[N_NODES * DD];
__device__ float g_Dh[N_NODES * DD];
__device__ float g_Eh[N_NODES * DD];
__device__ float g_hsum[N_NODES * DD];
__device__ float g_hpre[N_NODES * DD];
__device__ float g_enew[(size_t)N_EDGES * DD];
__device__ float g_stats[512];   // [0:128] e sum, [128:256] e sumsq, [256:384] h sum, [384:512] h sumsq
__device__ float g_bn[512];      // [0:128] e mean, [128:256] e invstd, [256:384] h mean, [384:512] h invstd

// ---------------------------------------------------------------------
// Node GEMM: out[M,128] = A[M,128] @ W^T + b   (W row-major [j][k])
// Block: 256 threads, 64-row tile, full W (k-major, padded) in smem.
// Thread map: warp w handles rows w*8..w*8+7; lane l handles cols 4l..4l+3.
// ---------------------------------------------------------------------
__global__ __launch_bounds__(256) void node_gemm_kernel(
    const float* __restrict__ A, const float* __restrict__ W,
    const float* __restrict__ bias, float* __restrict__ out, int M)
{
    extern __shared__ float s[];
    float* Wt = s;                      // [k][j], stride WT_STRIDE
    float* At = s + WT_FLOATS;          // [row][k]
    float* bs = At + AT_FLOATS;

    int tid = threadIdx.x, lane = tid & 31, warp = tid >> 5;
    int c0 = lane * 4;

    for (int idx = tid; idx < 128 * 128; idx += 256) {
        int j = idx >> 7, k = idx & 127;
        Wt[k * WT_STRIDE + j] = W[idx];
    }
    if (tid < 128) bs[tid] = bias[tid];

    int base = blockIdx.x * TM;
    __syncthreads();
    {
        const float4* Ag = (const float4*)A;
        float4* As = (float4*)At;
        #pragma unroll
        for (int i = 0; i < 8; i++) {
            int f4 = tid + i * 256;          // 0..2047, 32 float4 per row
            int row = f4 >> 5;
            float4 v = make_float4(0.f, 0.f, 0.f, 0.f);
            if (base + row < M) v = Ag[(size_t)base * 32 + f4];
            As[f4] = v;
        }
    }
    __syncthreads();

    float acc[8][4];
    #pragma unroll
    for (int r = 0; r < 8; r++) { acc[r][0] = acc[r][1] = acc[r][2] = acc[r][3] = 0.f; }

    for (int k = 0; k < 128; k += 4) {
        float4 w0 = *(const float4*)&Wt[(k + 0) * WT_STRIDE + c0];
        float4 w1 = *(const float4*)&Wt[(k + 1) * WT_STRIDE + c0];
        float4 w2 = *(const float4*)&Wt[(k + 2) * WT_STRIDE + c0];
        float4 w3 = *(const float4*)&Wt[(k + 3) * WT_STRIDE + c0];
        #pragma unroll
        for (int r = 0; r < 8; r++) {
            float4 a = *(const float4*)&At[(warp * 8 + r) * 128 + k];
            acc[r][0] += a.x * w0.x + a.y * w1.x + a.z * w2.x + a.w * w3.x;
            acc[r][1] += a.x * w0.y + a.y * w1.y + a.z * w2.y + a.w * w3.y;
            acc[r][2] += a.x * w0.z + a.y * w1.z + a.z * w2.z + a.w * w3.z;
            acc[r][3] += a.x * w0.w + a.y * w1.w + a.z * w2.w + a.w * w3.w;
        }
    }
    float4 bb = *(const float4*)&bs[c0];
    #pragma unroll
    for (int r = 0; r < 8; r++) {
        int row = base + warp * 8 + r;
        if (row < M) {
            float4 o = make_float4(acc[r][0] + bb.x, acc[r][1] + bb.y,
                                   acc[r][2] + bb.z, acc[r][3] + bb.w);
            *(float4*)&out[(size_t)row * 128 + c0] = o;
        }
    }
}

// ---------------------------------------------------------------------
// Fused edge kernel: Ce GEMM + full edge epilogue + scatter + e-stats
// ---------------------------------------------------------------------
__global__ __launch_bounds__(256) void edge_kernel(
    const float* __restrict__ e, const float* __restrict__ WC, const float* __restrict__ bC,
    const float* __restrict__ Bh, const float* __restrict__ Dh, const float* __restrict__ Eh,
    const int* __restrict__ src, const int* __restrict__ dst, const int* __restrict__ mask,
    const float* __restrict__ diff, const float* __restrict__ dist, const float* __restrict__ dirn,
    float* __restrict__ enew, float* __restrict__ hsumbuf, float* __restrict__ stats)
{
    extern __shared__ float s[];
    float* Wt = s;
    float* At = s + WT_FLOATS;
    float* bs = At + AT_FLOATS;

    int tid = threadIdx.x, lane = tid & 31, warp = tid >> 5;
    int c0 = lane * 4;

    for (int idx = tid; idx < 128 * 128; idx += 256) {
        int j = idx >> 7, k = idx & 127;
        Wt[k * WT_STRIDE + j] = WC[idx];
    }
    if (tid < 128) bs[tid] = bC[tid];

    float4 csum = make_float4(0.f, 0.f, 0.f, 0.f);
    float4 csq  = make_float4(0.f, 0.f, 0.f, 0.f);

    const int ntiles = N_EDGES / TM;   // 12500 exactly
    for (int tile = blockIdx.x; tile < ntiles; tile += gridDim.x) {
        int base = tile * TM;
        __syncthreads();
        {
            const float4* Ag = (const float4*)e + (size_t)base * 32;
            float4* As = (float4*)At;
            #pragma unroll
            for (int i = 0; i < 8; i++) As[tid + i * 256] = Ag[tid + i * 256];
        }
        __syncthreads();

        float acc[8][4];
        #pragma unroll
        for (int r = 0; r < 8; r++) { acc[r][0] = acc[r][1] = acc[r][2] = acc[r][3] = 0.f; }

        for (int k = 0; k < 128; k += 4) {
            float4 w0 = *(const float4*)&Wt[(k + 0) * WT_STRIDE + c0];
            float4 w1 = *(const float4*)&Wt[(k + 1) * WT_STRIDE + c0];
            float4 w2 = *(const float4*)&Wt[(k + 2) * WT_STRIDE + c0];
            float4 w3 = *(const float4*)&Wt[(k + 3) * WT_STRIDE + c0];
            #pragma unroll
            for (int r = 0; r < 8; r++) {
                float4 a = *(const float4*)&At[(warp * 8 + r) * 128 + k];
                acc[r][0] += a.x * w0.x + a.y * w1.x + a.z * w2.x + a.w * w3.x;
                acc[r][1] += a.x * w0.y + a.y * w1.y + a.z * w2.y + a.w * w3.y;
                acc[r][2] += a.x * w0.z + a.y * w1.z + a.z * w2.z + a.w * w3.z;
                acc[r][3] += a.x * w0.w + a.y * w1.w + a.z * w2.w + a.w * w3.w;
            }
        }

        float4 bb = *(const float4*)&bs[c0];
        #pragma unroll
        for (int r = 0; r < 8; r++) {
            int i = base + warp * 8 + r;
            int si = src[i], di = dst[i];
            float4 dh  = *(const float4*)&Dh[(size_t)di * 128 + c0];
            float4 ehv = *(const float4*)&Eh[(size_t)si * 128 + c0];
            float4 de = make_float4(dh.x - ehv.x, dh.y - ehv.y, dh.z - ehv.z, dh.w - ehv.w);
            float4 en = make_float4(de.x + acc[r][0] + bb.x, de.y + acc[r][1] + bb.y,
                                    de.z + acc[r][2] + bb.z, de.w + acc[r][3] + bb.w);
            float ss = en.x * en.x + en.y * en.y + en.z * en.z + en.w * en.w;
            #pragma unroll
            for (int o = 16; o > 0; o >>= 1) ss += __shfl_xor_sync(0xffffffffu, ss, o);
            float sigma = expf(-0.5f * sqrtf(ss));

            float ddv = dist[i];
            float df0 = diff[2 * i], df1 = diff[2 * i + 1];
            float ed0, ed1;
            if (ddv > 0.f) { ed0 = df0 / ddv; ed1 = df1 / ddv; } else { ed0 = df0; ed1 = df1; }
            float vs0 = dirn[2 * si], vs1 = dirn[2 * si + 1];
            float vd0 = dirn[2 * di], vd1 = dirn[2 * di + 1];
            float uv  = vs0 * vd0 + vs1 * vd1;
            float ehd = ed0 * vd0 + ed1 * vd1;
            float fgate = 0.5f * (1.f - ehd) * uv * sigma;
            float gate = (mask[i] == 1) ? fgate : sigma;

            float4 bh = *(const float4*)&Bh[(size_t)si * 128 + c0];
            float4 hs = make_float4((bh.x + de.x) * gate, (bh.y + de.y) * gate,
                                    (bh.z + de.z) * gate, (bh.w + de.w) * gate);
            atomicAdd((float4*)&hsumbuf[(size_t)di * 128 + c0], hs);
            *(float4*)&enew[(size_t)i * 128 + c0] = en;

            csum.x += en.x; csum.y += en.y; csum.z += en.z; csum.w += en.w;
            csq.x += en.x * en.x; csq.y += en.y * en.y;
            csq.z += en.z * en.z; csq.w += en.w * en.w;
        }
    }

    // block-level column-stat reduction into global stats
    __syncthreads();
    float* rs = At;           // 8 warps * 128 cols
    float* rq = At + 1024;
    *(float4*)&rs[warp * 128 + c0] = csum;
    *(float4*)&rq[warp * 128 + c0] = csq;
    __syncthreads();
    if (tid < 128) {
        float s1 = 0.f, q1 = 0.f;
        #pragma unroll
        for (int w = 0; w < 8; w++) { s1 += rs[w * 128 + tid]; q1 += rq[w * 128 + tid]; }
        atomicAdd(&stats[tid], s1);
        atomicAdd(&stats[128 + tid], q1);
    }
}

// ---------------------------------------------------------------------
// hpre = Ah + hsum; accumulate h column stats
// ---------------------------------------------------------------------
__global__ __launch_bounds__(256) void hpre_kernel(
    const float* __restrict__ Ah, const float* __restrict__ hsumbuf,
    float* __restrict__ hpre, float* __restrict__ stats)
{
    __shared__ float red[2048];
    int tid = threadIdx.x, lane = tid & 31, warp = tid >> 5;
    int c0 = lane * 4;
    int gw = blockIdx.x * 8 + warp;
    int nw = gridDim.x * 8;

    float4 csum = make_float4(0.f, 0.f, 0.f, 0.f);
    float4 csq  = make_float4(0.f, 0.f, 0.f, 0.f);

    for (int r = gw; r < N_NODES; r += nw) {
        float4 a = *(const float4*)&Ah[(size_t)r * 128 + c0];
        float4 hv = *(const float4*)&hsumbuf[(size_t)r * 128 + c0];
        float4 p = make_float4(a.x + hv.x, a.y + hv.y, a.z + hv.z, a.w + hv.w);
        *(float4*)&hpre[(size_t)r * 128 + c0] = p;
        csum.x += p.x; csum.y += p.y; csum.z += p.z; csum.w += p.w;
        csq.x += p.x * p.x; csq.y += p.y * p.y; csq.z += p.z * p.z; csq.w += p.w * p.w;
    }
    *(float4*)&red[warp * 128 + c0] = csum;
    *(float4*)&red[1024 + warp * 128 + c0] = csq;
    __syncthreads();
    if (tid < 128) {
        float s1 = 0.f, q1 = 0.f;
        #pragma unroll
        for (int w = 0; w < 8; w++) { s1 += red[w * 128 + tid]; q1 += red[1024 + w * 128 + tid]; }
        atomicAdd(&stats[256 + tid], s1);
        atomicAdd(&stats[384 + tid], q1);
    }
}

// ---------------------------------------------------------------------
__global__ void finalize_kernel(const float* __restrict__ st, float* __restrict__ bnout, float invcount)
{
    int t = threadIdx.x;
    if (t < 128) {
        float mean = st[t] * invcount;
        float var  = st[128 + t] * invcount - mean * mean;
        bnout[t] = mean;
        bnout[128 + t] = rsqrtf(var + EPSBN);
    }
}

// out = resid + relu(gamma*(pre-mean)*invstd + beta), elementwise, float4
__global__ void apply_kernel(const float* __restrict__ pre, const float* __restrict__ resid,
                             const float* __restrict__ gamma, const float* __restrict__ beta,
                             const float* __restrict__ bn, float* __restrict__ out, int total4)
{
    int idx = blockIdx.x * blockDim.x + threadIdx.x;
    int stride = gridDim.x * blockDim.x;
    for (; idx < total4; idx += stride) {
        int c0 = (idx & 31) * 4;
        float4 m  = *(const float4*)&bn[c0];
        float4 iv = *(const float4*)&bn[128 + c0];
        float4 g  = *(const float4*)&gamma[c0];
        float4 b  = *(const float4*)&beta[c0];
        float4 p  = ((const float4*)pre)[idx];
        float4 rr = ((const float4*)resid)[idx];
        float4 o;
        o.x = fmaxf((p.x - m.x) * iv.x * g.x + b.x, 0.f) + rr.x;
        o.y = fmaxf((p.y - m.y) * iv.y * g.y + b.y, 0.f) + rr.y;
        o.z = fmaxf((p.z - m.z) * iv.z * g.z + b.z, 0.f) + rr.z;
        o.w = fmaxf((p.w - m.w) * iv.w * g.w + b.w, 0.f) + rr.w;
        ((float4*)out)[idx] = o;
    }
}

// ---------------------------------------------------------------------
extern "C" void kernel_launch(void* const* d_in, const int* in_sizes, int n_in,
                              void* d_out, int out_size)
{
    const float* h    = (const float*)d_in[0];
    const float* e    = (const float*)d_in[1];
    const int*   src  = (const int*)d_in[2];
    const int*   dst  = (const int*)d_in[3];
    const int*   mask = (const int*)d_in[4];
    const float* diff = (const float*)d_in[5];
    const float* dist = (const float*)d_in[6];
    const float* dirn = (const float*)d_in[7];
    const float* WA = (const float*)d_in[8];   const float* bA = (const float*)d_in[9];
    const float* WB = (const float*)d_in[10];  const float* bB = (const float*)d_in[11];
    const float* WC = (const float*)d_in[12];  const float* bC = (const float*)d_in[13];
    const float* WD = (const float*)d_in[14];  const float* bD = (const float*)d_in[15];
    const float* WE = (const float*)d_in[16];  const float* bE = (const float*)d_in[17];
    const float* gh = (const float*)d_in[18];  const float* betah = (const float*)d_in[19];
    const float* ge = (const float*)d_in[20];  const float* betae = (const float*)d_in[21];
    float* out = (float*)d_out;

    float *Ah, *Bh, *Dh, *Eh, *hsum, *hpre, *enew, *stats, *bn;
    cudaGetSymbolAddress((void**)&Ah,   g_Ah);
    cudaGetSymbolAddress((void**)&Bh,   g_Bh);
    cudaGetSymbolAddress((void**)&Dh,   g_Dh);
    cudaGetSymbolAddress((void**)&Eh,   g_Eh);
    cudaGetSymbolAddress((void**)&hsum, g_hsum);
    cudaGetSymbolAddress((void**)&hpre, g_hpre);
    cudaGetSymbolAddress((void**)&enew, g_enew);
    cudaGetSymbolAddress((void**)&stats, g_stats);
    cudaGetSymbolAddress((void**)&bn,   g_bn);

    cudaFuncSetAttribute(node_gemm_kernel, cudaFuncAttributeMaxDynamicSharedMemorySize, SMEM_BYTES);
    cudaFuncSetAttribute(edge_kernel,      cudaFuncAttributeMaxDynamicSharedMemorySize, SMEM_BYTES);

    cudaMemsetAsync(hsum, 0, (size_t)N_NODES * DD * sizeof(float));
    cudaMemsetAsync(stats, 0, 512 * sizeof(float));

    int node_tiles = (N_NODES + TM - 1) / TM;   // 782
    node_gemm_kernel<<<node_tiles, 256, SMEM_BYTES>>>(h, WA, bA, Ah, N_NODES);
    node_gemm_kernel<<<node_tiles, 256, SMEM_BYTES>>>(h, WB, bB, Bh, N_NODES);
    node_gemm_kernel<<<node_tiles, 256, SMEM_BYTES>>>(h, WD, bD, Dh, N_NODES);
    node_gemm_kernel<<<node_tiles, 256, SMEM_BYTES>>>(h, WE, bE, Eh, N_NODES);

    edge_kernel<<<296, 256, SMEM_BYTES>>>(e, WC, bC, Bh, Dh, Eh, src, dst, mask,
                                          diff, dist, dirn, enew, hsum, stats);

    finalize_kernel<<<1, 128>>>(stats, bn, 1.0f / (float)N_EDGES);
    hpre_kernel<<<296, 256>>>(Ah, hsum, hpre, stats);
    finalize_kernel<<<1, 128>>>(stats + 256, bn + 256, 1.0f / (float)N_NODES);

    apply_kernel<<<1024, 256>>>(hpre, h, gh, betah, bn + 256, out, N_NODES * 32);
    apply_kernel<<<4096, 256>>>(enew, e, ge, betae, bn, out + (size_t)N_NODES * DD, N_EDGES * 32);
}

// round 3
// speedup vs baseline: 1.0017x; 1.0017x over previous
#include <cuda_runtime.h>
#include <math.h>

#define N_NODES 50000
#define N_EDGES 800000
#define DD      128
#define EPSBN   1e-5f

#define TM 64                   // rows (nodes or edges) per GEMM tile
#define WT_STRIDE 132           // padded k-major W stride (conflict-free)
#define WT_FLOATS (128 * WT_STRIDE)
#define AT_FLOATS (TM * 128)
#define SMEM_FLOATS (WT_FLOATS + AT_FLOATS + 128)
#define SMEM_BYTES  (SMEM_FLOATS * 4)

// ---------------- scratch (static device allocations) ----------------
__device__ float g_Ah[N_NODES * DD];
__device__ float g_Bh[N_NODES * DD];
__device__ float g_Dh[N_NODES * DD];
__device__ float g_Eh[N_NODES * DD];
__device__ float g_hsum[N_NODES * DD];
__device__ float g_hpre[N_NODES * DD];
__device__ float g_enew[(size_t)N_EDGES * DD];
__device__ float g_stats[512];   // [0:128] e sum, [128:256] e sumsq, [256:384] h sum, [384:512] h sumsq
__device__ float g_bn[512];      // [0:128] e mean, [128:256] e invstd, [256:384] h mean, [384:512] h invstd

// ---------------------------------------------------------------------
// Node GEMM: out[M,128] = A[M,128] @ W^T + b   (W row-major [j][k])
// Block: 256 threads, 64-row tile, full W (k-major, padded) in smem.
// Thread map: warp w handles rows w*8..w*8+7; lane l handles cols 4l..4l+3.
// ---------------------------------------------------------------------
__global__ __launch_bounds__(256) void node_gemm_kernel(
    const float* __restrict__ A, const float* __restrict__ W,
    const float* __restrict__ bias, float* __restrict__ out, int M)
{
    extern __shared__ float s[];
    float* Wt = s;                      // [k][j], stride WT_STRIDE
    float* At = s + WT_FLOATS;          // [row][k]
    float* bs = At + AT_FLOATS;

    int tid = threadIdx.x, lane = tid & 31, warp = tid >> 5;
    int c0 = lane * 4;

    for (int idx = tid; idx < 128 * 128; idx += 256) {
        int j = idx >> 7, k = idx & 127;
        Wt[k * WT_STRIDE + j] = W[idx];
    }
    if (tid < 128) bs[tid] = bias[tid];

    int base = blockIdx.x * TM;
    __syncthreads();
    {
        const float4* Ag = (const float4*)A;
        float4* As = (float4*)At;
        #pragma unroll
        for (int i = 0; i < 8; i++) {
            int f4 = tid + i * 256;          // 0..2047, 32 float4 per row
            int row = f4 >> 5;
            float4 v = make_float4(0.f, 0.f, 0.f, 0.f);
            if (base + row < M) v = Ag[(size_t)base * 32 + f4];
            As[f4] = v;
        }
    }
    __syncthreads();

    float acc[8][4];
    #pragma unroll
    for (int r = 0; r < 8; r++) { acc[r][0] = acc[r][1] = acc[r][2] = acc[r][3] = 0.f; }

    for (int k = 0; k < 128; k += 4) {
        float4 w0 = *(const float4*)&Wt[(k + 0) * WT_STRIDE + c0];
        float4 w1 = *(const float4*)&Wt[(k + 1) * WT_STRIDE + c0];
        float4 w2 = *(const float4*)&Wt[(k + 2) * WT_STRIDE + c0];
        float4 w3 = *(const float4*)&Wt[(k + 3) * WT_STRIDE + c0];
        #pragma unroll
        for (int r = 0; r < 8; r++) {
            float4 a = *(const float4*)&At[(warp * 8 + r) * 128 + k];
            acc[r][0] += a.x * w0.x + a.y * w1.x + a.z * w2.x + a.w * w3.x;
            acc[r][1] += a.x * w0.y + a.y * w1.y + a.z * w2.y + a.w * w3.y;
            acc[r][2] += a.x * w0.z + a.y * w1.z + a.z * w2.z + a.w * w3.z;
            acc[r][3] += a.x * w0.w + a.y * w1.w + a.z * w2.w + a.w * w3.w;
        }
    }
    float4 bb = *(const float4*)&bs[c0];
    #pragma unroll
    for (int r = 0; r < 8; r++) {
        int row = base + warp * 8 + r;
        if (row < M) {
            float4 o = make_float4(acc[r][0] + bb.x, acc[r][1] + bb.y,
                                   acc[r][2] + bb.z, acc[r][3] + bb.w);
            *(float4*)&out[(size_t)row * 128 + c0] = o;
        }
    }
}

// ---------------------------------------------------------------------
// Fused edge kernel: Ce GEMM + full edge epilogue + scatter + e-stats
// ---------------------------------------------------------------------
__global__ __launch_bounds__(256) void edge_kernel(
    const float* __restrict__ e, const float* __restrict__ WC, const float* __restrict__ bC,
    const float* __restrict__ Bh, const float* __restrict__ Dh, const float* __restrict__ Eh,
    const int* __restrict__ src, const int* __restrict__ dst, const int* __restrict__ mask,
    const float* __restrict__ diff, const float* __restrict__ dist, const float* __restrict__ dirn,
    float* __restrict__ enew, float* __restrict__ hsumbuf, float* __restrict__ stats)
{
    extern __shared__ float s[];
    float* Wt = s;
    float* At = s + WT_FLOATS;
    float* bs = At + AT_FLOATS;

    int tid = threadIdx.x, lane = tid & 31, warp = tid >> 5;
    int c0 = lane * 4;

    for (int idx = tid; idx < 128 * 128; idx += 256) {
        int j = idx >> 7, k = idx & 127;
        Wt[k * WT_STRIDE + j] = WC[idx];
    }
    if (tid < 128) bs[tid] = bC[tid];

    float4 csum = make_float4(0.f, 0.f, 0.f, 0.f);
    float4 csq  = make_float4(0.f, 0.f, 0.f, 0.f);

    const int ntiles = N_EDGES / TM;   // 12500 exactly
    for (int tile = blockIdx.x; tile < ntiles; tile += gridDim.x) {
        int base = tile * TM;
        __syncthreads();
        {
            const float4* Ag = (const float4*)e + (size_t)base * 32;
            float4* As = (float4*)At;
            #pragma unroll
            for (int i = 0; i < 8; i++) As[tid + i * 256] = Ag[tid + i * 256];
        }
        __syncthreads();

        float acc[8][4];
        #pragma unroll
        for (int r = 0; r < 8; r++) { acc[r][0] = acc[r][1] = acc[r][2] = acc[r][3] = 0.f; }

        for (int k = 0; k < 128; k += 4) {
            float4 w0 = *(const float4*)&Wt[(k + 0) * WT_STRIDE + c0];
            float4 w1 = *(const float4*)&Wt[(k + 1) * WT_STRIDE + c0];
            float4 w2 = *(const float4*)&Wt[(k + 2) * WT_STRIDE + c0];
            float4 w3 = *(const float4*)&Wt[(k + 3) * WT_STRIDE + c0];
            #pragma unroll
            for (int r = 0; r < 8; r++) {
                float4 a = *(const float4*)&At[(warp * 8 + r) * 128 + k];
                acc[r][0] += a.x * w0.x + a.y * w1.x + a.z * w2.x + a.w * w3.x;
                acc[r][1] += a.x * w0.y + a.y * w1.y + a.z * w2.y + a.w * w3.y;
                acc[r][2] += a.x * w0.z + a.y * w1.z + a.z * w2.z + a.w * w3.z;
                acc[r][3] += a.x * w0.w + a.y * w1.w + a.z * w2.w + a.w * w3.w;
            }
        }

        float4 bb = *(const float4*)&bs[c0];
        #pragma unroll
        for (int r = 0; r < 8; r++) {
            int i = base + warp * 8 + r;
            int si = src[i], di = dst[i];
            float4 dh  = *(const float4*)&Dh[(size_t)di * 128 + c0];
            float4 ehv = *(const float4*)&Eh[(size_t)si * 128 + c0];
            float4 de = make_float4(dh.x - ehv.x, dh.y - ehv.y, dh.z - ehv.z, dh.w - ehv.w);
            float4 en = make_float4(de.x + acc[r][0] + bb.x, de.y + acc[r][1] + bb.y,
                                    de.z + acc[r][2] + bb.z, de.w + acc[r][3] + bb.w);
            float ss = en.x * en.x + en.y * en.y + en.z * en.z + en.w * en.w;
            #pragma unroll
            for (int o = 16; o > 0; o >>= 1) ss += __shfl_xor_sync(0xffffffffu, ss, o);
            float sigma = expf(-0.5f * sqrtf(ss));

            float ddv = dist[i];
            float df0 = diff[2 * i], df1 = diff[2 * i + 1];
            float ed0, ed1;
            if (ddv > 0.f) { ed0 = df0 / ddv; ed1 = df1 / ddv; } else { ed0 = df0; ed1 = df1; }
            float vs0 = dirn[2 * si], vs1 = dirn[2 * si + 1];
            float vd0 = dirn[2 * di], vd1 = dirn[2 * di + 1];
            float uv  = vs0 * vd0 + vs1 * vd1;
            float ehd = ed0 * vd0 + ed1 * vd1;
            float fgate = 0.5f * (1.f - ehd) * uv * sigma;
            float gate = (mask[i] == 1) ? fgate : sigma;

            float4 bh = *(const float4*)&Bh[(size_t)si * 128 + c0];
            float4 hs = make_float4((bh.x + de.x) * gate, (bh.y + de.y) * gate,
                                    (bh.z + de.z) * gate, (bh.w + de.w) * gate);
            atomicAdd((float4*)&hsumbuf[(size_t)di * 128 + c0], hs);
            *(float4*)&enew[(size_t)i * 128 + c0] = en;

            csum.x += en.x; csum.y += en.y; csum.z += en.z; csum.w += en.w;
            csq.x += en.x * en.x; csq.y += en.y * en.y;
            csq.z += en.z * en.z; csq.w += en.w * en.w;
        }
    }

    // block-level column-stat reduction into global stats
    __syncthreads();
    float* rs = At;           // 8 warps * 128 cols
    float* rq = At + 1024;
    *(float4*)&rs[warp * 128 + c0] = csum;
    *(float4*)&rq[warp * 128 + c0] = csq;
    __syncthreads();
    if (tid < 128) {
        float s1 = 0.f, q1 = 0.f;
        #pragma unroll
        for (int w = 0; w < 8; w++) { s1 += rs[w * 128 + tid]; q1 += rq[w * 128 + tid]; }
        atomicAdd(&stats[tid], s1);
        atomicAdd(&stats[128 + tid], q1);
    }
}

// ---------------------------------------------------------------------
// hpre = Ah + hsum; accumulate h column stats
// ---------------------------------------------------------------------
__global__ __launch_bounds__(256) void hpre_kernel(
    const float* __restrict__ Ah, const float* __restrict__ hsumbuf,
    float* __restrict__ hpre, float* __restrict__ stats)
{
    __shared__ float red[2048];
    int tid = threadIdx.x, lane = tid & 31, warp = tid >> 5;
    int c0 = lane * 4;
    int gw = blockIdx.x * 8 + warp;
    int nw = gridDim.x * 8;

    float4 csum = make_float4(0.f, 0.f, 0.f, 0.f);
    float4 csq  = make_float4(0.f, 0.f, 0.f, 0.f);

    for (int r = gw; r < N_NODES; r += nw) {
        float4 a = *(const float4*)&Ah[(size_t)r * 128 + c0];
        float4 hv = *(const float4*)&hsumbuf[(size_t)r * 128 + c0];
        float4 p = make_float4(a.x + hv.x, a.y + hv.y, a.z + hv.z, a.w + hv.w);
        *(float4*)&hpre[(size_t)r * 128 + c0] = p;
        csum.x += p.x; csum.y += p.y; csum.z += p.z; csum.w += p.w;
        csq.x += p.x * p.x; csq.y += p.y * p.y; csq.z += p.z * p.z; csq.w += p.w * p.w;
    }
    *(float4*)&red[warp * 128 + c0] = csum;
    *(float4*)&red[1024 + warp * 128 + c0] = csq;
    __syncthreads();
    if (tid < 128) {
        float s1 = 0.f, q1 = 0.f;
        #pragma unroll
        for (int w = 0; w < 8; w++) { s1 += red[w * 128 + tid]; q1 += red[1024 + w * 128 + tid]; }
        atomicAdd(&stats[256 + tid], s1);
        atomicAdd(&stats[384 + tid], q1);
    }
}

// ---------------------------------------------------------------------
__global__ void finalize_kernel(const float* __restrict__ st, float* __restrict__ bnout, float invcount)
{
    int t = threadIdx.x;
    if (t < 128) {
        float mean = st[t] * invcount;
        float var  = st[128 + t] * invcount - mean * mean;
        bnout[t] = mean;
        bnout[128 + t] = rsqrtf(var + EPSBN);
    }
}

// out = resid + relu(gamma*(pre-mean)*invstd + beta), elementwise, float4
__global__ void apply_kernel(const float* __restrict__ pre, const float* __restrict__ resid,
                             const float* __restrict__ gamma, const float* __restrict__ beta,
                             const float* __restrict__ bn, float* __restrict__ out, int total4)
{
    int idx = blockIdx.x * blockDim.x + threadIdx.x;
    int stride = gridDim.x * blockDim.x;
    for (; idx < total4; idx += stride) {
        int c0 = (idx & 31) * 4;
        float4 m  = *(const float4*)&bn[c0];
        float4 iv = *(const float4*)&bn[128 + c0];
        float4 g  = *(const float4*)&gamma[c0];
        float4 b  = *(const float4*)&beta[c0];
        float4 p  = ((const float4*)pre)[idx];
        float4 rr = ((const float4*)resid)[idx];
        float4 o;
        o.x = fmaxf((p.x - m.x) * iv.x * g.x + b.x, 0.f) + rr.x;
        o.y = fmaxf((p.y - m.y) * iv.y * g.y + b.y, 0.f) + rr.y;
        o.z = fmaxf((p.z - m.z) * iv.z * g.z + b.z, 0.f) + rr.z;
        o.w = fmaxf((p.w - m.w) * iv.w * g.w + b.w, 0.f) + rr.w;
        ((float4*)out)[idx] = o;
    }
}

// ---------------------------------------------------------------------
extern "C" void kernel_launch(void* const* d_in, const int* in_sizes, int n_in,
                              void* d_out, int out_size)
{
    const float* h    = (const float*)d_in[0];
    const float* e    = (const float*)d_in[1];
    const int*   src  = (const int*)d_in[2];
    const int*   dst  = (const int*)d_in[3];
    const int*   mask = (const int*)d_in[4];
    const float* diff = (const float*)d_in[5];
    const float* dist = (const float*)d_in[6];
    const float* dirn = (const float*)d_in[7];
    const float* WA = (const float*)d_in[8];   const float* bA = (const float*)d_in[9];
    const float* WB = (const float*)d_in[10];  const float* bB = (const float*)d_in[11];
    const float* WC = (const float*)d_in[12];  const float* bC = (const float*)d_in[13];
    const float* WD = (const float*)d_in[14];  const float* bD = (const float*)d_in[15];
    const float* WE = (const float*)d_in[16];  const float* bE = (const float*)d_in[17];
    const float* gh = (const float*)d_in[18];  const float* betah = (const float*)d_in[19];
    const float* ge = (const float*)d_in[20];  const float* betae = (const float*)d_in[21];
    float* out = (float*)d_out;

    float *Ah, *Bh, *Dh, *Eh, *hsum, *hpre, *enew, *stats, *bn;
    cudaGetSymbolAddress((void**)&Ah,   g_Ah);
    cudaGetSymbolAddress((void**)&Bh,   g_Bh);
    cudaGetSymbolAddress((void**)&Dh,   g_Dh);
    cudaGetSymbolAddress((void**)&Eh,   g_Eh);
    cudaGetSymbolAddress((void**)&hsum, g_hsum);
    cudaGetSymbolAddress((void**)&hpre, g_hpre);
    cudaGetSymbolAddress((void**)&enew, g_enew);
    cudaGetSymbolAddress((void**)&stats, g_stats);
    cudaGetSymbolAddress((void**)&bn,   g_bn);

    cudaFuncSetAttribute(node_gemm_kernel, cudaFuncAttributeMaxDynamicSharedMemorySize, SMEM_BYTES);
    cudaFuncSetAttribute(edge_kernel,      cudaFuncAttributeMaxDynamicSharedMemorySize, SMEM_BYTES);

    cudaMemsetAsync(hsum, 0, (size_t)N_NODES * DD * sizeof(float));
    cudaMemsetAsync(stats, 0, 512 * sizeof(float));

    int node_tiles = (N_NODES + TM - 1) / TM;   // 782
    node_gemm_kernel<<<node_tiles, 256, SMEM_BYTES>>>(h, WA, bA, Ah, N_NODES);
    node_gemm_kernel<<<node_tiles, 256, SMEM_BYTES>>>(h, WB, bB, Bh, N_NODES);
    node_gemm_kernel<<<node_tiles, 256, SMEM_BYTES>>>(h, WD, bD, Dh, N_NODES);
    node_gemm_kernel<<<node_tiles, 256, SMEM_BYTES>>>(h, WE, bE, Eh, N_NODES);

    edge_kernel<<<296, 256, SMEM_BYTES>>>(e, WC, bC, Bh, Dh, Eh, src, dst, mask,
                                          diff, dist, dirn, enew, hsum, stats);

    finalize_kernel<<<1, 128>>>(stats, bn, 1.0f / (float)N_EDGES);
    hpre_kernel<<<296, 256>>>(Ah, hsum, hpre, stats);
    finalize_kernel<<<1, 128>>>(stats + 256, bn + 256, 1.0f / (float)N_NODES);

    apply_kernel<<<1024, 256>>>(hpre, h, gh, betah, bn + 256, out, N_NODES * 32);
    apply_kernel<<<4096, 256>>>(enew, e, ge, betae, bn, out + (size_t)N_NODES * DD, N_EDGES * 32);
}